// round 3
// baseline (speedup 1.0000x reference)
#include <cuda_runtime.h>
#include <math.h>

#define N_AG   2048
#define HID    64
#define MED    128
#define SOC    64
#define ZK     256     // z layout: r[0:128] | e[128:192] | h[192:256]
#define NGATE  256
#define NSTEP  20
#define MAXNB  32
#define AB     16      // agents per block
#define TPB    256

// ---------------- device scratch (static, no runtime alloc) ----------------
__device__ float d_h[2 * N_AG * HID];          // double-buffered hidden state
__device__ float d_c[N_AG * HID];              // cell state
__device__ float d_Wse[SOC * HID];             // collapsed social weight (sum over 9 window cells)
__device__ int   d_nbc[NSTEP * N_AG];          // neighbor counts per (t, agent)
__device__ int   d_nbi[NSTEP * N_AG * MAXNB];  // neighbor indices (ascending j)

__device__ __forceinline__ float sigm(float x) { return 1.0f / (1.0f + expf(-x)); }

// ---------------- init: copy h0/c0, collapse W_soc, zero tail frames -------
__global__ __launch_bounds__(256) void init_kernel(
    const float* __restrict__ h0, const float* __restrict__ c0,
    const float* __restrict__ W_soc, float* __restrict__ out)
{
    int i = blockIdx.x * blockDim.x + threadIdx.x;
    if (i < N_AG * HID) { d_h[i] = h0[i]; d_c[i] = c0[i]; }
    if (i < SOC * HID) {
        int o = i >> 6, k = i & 63;
        float s = 0.f;
        #pragma unroll
        for (int w = 0; w < 9; w++) s += W_soc[o * 576 + w * 64 + k];
        d_Wse[i] = s;
    }
    if (i < 4 * N_AG * 2) out[NSTEP * N_AG * 2 + i] = 0.f;  // frames 20..23 = 0
}

// ---------------- neighbor precompute: grid = NSTEP*8 blocks ---------------
// Each block handles (t = blockIdx.x>>3, agents [pass*256, pass*256+256)).
// Replicates ref exactly: lt = min(coords) - 1.2f; p = floor((c-lt)/0.3f);
// masked -> cell (0,0); agent i gathers cell p_i - (1,1).
__global__ __launch_bounds__(256) void nbr_kernel(
    const float* __restrict__ X, const float* __restrict__ masks)
{
    int t    = blockIdx.x >> 3;
    int pass = blockIdx.x & 7;
    __shared__ __align__(16) int keys[N_AG];
    __shared__ float rmin[16];
    const float* xt = X + t * N_AG * 2;
    int tid = threadIdx.x;

    float mnx = 3.4e38f, mny = 3.4e38f;
    for (int i = tid; i < N_AG; i += TPB) {
        mnx = fminf(mnx, xt[2 * i]);
        mny = fminf(mny, xt[2 * i + 1]);
    }
    #pragma unroll
    for (int o = 16; o; o >>= 1) {
        mnx = fminf(mnx, __shfl_xor_sync(0xffffffffu, mnx, o));
        mny = fminf(mny, __shfl_xor_sync(0xffffffffu, mny, o));
    }
    if ((tid & 31) == 0) { rmin[tid >> 5] = mnx; rmin[8 + (tid >> 5)] = mny; }
    __syncthreads();
    if (tid == 0) {
        float a = rmin[0], b = rmin[8];
        for (int w = 1; w < 8; w++) { a = fminf(a, rmin[w]); b = fminf(b, rmin[8 + w]); }
        rmin[0] = a - 1.2f;  // margin = 2*N_SIZE*CELL = 1.2 (fp32)
        rmin[8] = b - 1.2f;
    }
    __syncthreads();
    float ltx = rmin[0], lty = rmin[8];

    for (int i = tid; i < N_AG; i += TPB) {
        int p0 = (int)floorf(__fdiv_rn(xt[2 * i]     - ltx, 0.3f));
        int p1 = (int)floorf(__fdiv_rn(xt[2 * i + 1] - lty, 0.3f));
        if (masks[t * N_AG + i] == 0.0f) { p0 = 0; p1 = 0; }
        keys[i] = p0 * 32768 + p1;   // p components are small non-negative ints
    }
    __syncthreads();

    int i = pass * 256 + tid;
    int q = keys[i] - 32769;         // key of cell (p0-1, p1-1); masked -> negative, no match
    int cnt = 0;
    int* dst = d_nbi + (t * N_AG + i) * MAXNB;
    const int4* k4 = (const int4*)keys;
    for (int j4 = 0; j4 < N_AG / 4; j4++) {
        int4 kv = k4[j4];            // broadcast across warp (same address all lanes)
        int j = j4 * 4;
        if (kv.x == q && cnt < MAXNB) dst[cnt++] = j;
        if (kv.y == q && cnt < MAXNB) dst[cnt++] = j + 1;
        if (kv.z == q && cnt < MAXNB) dst[cnt++] = j + 2;
        if (kv.w == q && cnt < MAXNB) dst[cnt++] = j + 3;
    }
    d_nbc[t * N_AG + i] = cnt;
}

// ---------------- fused per-step kernel ------------------------------------
// grid = 128 blocks x 256 threads; each block owns 16 agents.
__global__ __launch_bounds__(256) void step_kernel(
    int t,
    const float* __restrict__ X, const float* __restrict__ masks,
    const float* __restrict__ W_in, const float* __restrict__ b_in,
    const float* __restrict__ b_soc,
    const float* __restrict__ W_ih, const float* __restrict__ W_hh,
    const float* __restrict__ b_ih, const float* __restrict__ b_hh,
    const float* __restrict__ W_out, const float* __restrict__ b_out,
    float* out)
{
    __shared__ __align__(16) float z_sm[AB][ZK];     // [r | e | h] per agent
    __shared__ float g_sm[AB][NGATE];
    __shared__ float cv_sm[AB][HID];                 // cell_val, later reused for h_new

    int tid = threadIdx.x;
    int ab  = blockIdx.x * AB;
    const float* hcur = d_h + (t & 1) * N_AG * HID;
    float*       hnxt = d_h + ((t + 1) & 1) * N_AG * HID;
    const float* mrow = masks + t * N_AG;
    // ref: frames 0..10 feed X[t]; frames >=11 feed out[t-2] (faithful off-by-one)
    const float* xin = (t <= 10) ? (X + t * N_AG * 2) : (out + (t - 2) * N_AG * 2);

    // ---- social gather (cell_val) + stage h into z tail ----
    for (int w = tid; w < AB * HID; w += TPB) {
        int a = w >> 6, d = w & 63;
        int i = ab + a;
        int cnt = d_nbc[t * N_AG + i];
        const int* nb = d_nbi + (t * N_AG + i) * MAXNB;
        float s = 0.f;
        for (int jj = 0; jj < cnt; jj++) s += hcur[nb[jj] * HID + d];
        cv_sm[a][d] = s * mrow[i];                 // Hf = tile(cell_val)*mask
        z_sm[a][192 + d] = hcur[i * HID + d];
    }
    // ---- r = relu(W_in @ x + b_in) ----
    for (int w = tid; w < AB * MED; w += TPB) {
        int a = w >> 7, o = w & 127;
        int i = ab + a;
        float v = fmaf(W_in[o * 2], xin[i * 2],
                  fmaf(W_in[o * 2 + 1], xin[i * 2 + 1], b_in[o]));
        z_sm[a][o] = fmaxf(v, 0.f);
    }
    __syncthreads();
    // ---- e = relu(W_eff @ cell_val + b_soc) ----
    for (int w = tid; w < AB * SOC; w += TPB) {
        int a = w >> 6, o = w & 63;
        float acc = b_soc[o];
        const float* Ws = d_Wse + o * HID;
        #pragma unroll 8
        for (int k = 0; k < HID; k++) acc = fmaf(Ws[k], cv_sm[a][k], acc);
        z_sm[a][MED + o] = fmaxf(acc, 0.f);
    }
    __syncthreads();
    // ---- gate GEMM: thread g computes gate g for all 16 agents ----
    {
        int g = tid;
        float acc[AB];
        #pragma unroll
        for (int a = 0; a < AB; a++) acc[a] = 0.f;
        const float4* wih = (const float4*)(W_ih + g * 192);
        #pragma unroll 4
        for (int k4 = 0; k4 < 48; k4++) {
            float4 wv = wih[k4];
            #pragma unroll
            for (int a = 0; a < AB; a++) {
                float4 zv = *(const float4*)&z_sm[a][k4 * 4];  // warp-broadcast LDS.128
                acc[a] = fmaf(wv.x, zv.x, fmaf(wv.y, zv.y,
                         fmaf(wv.z, zv.z, fmaf(wv.w, zv.w, acc[a]))));
            }
        }
        const float4* whh = (const float4*)(W_hh + g * HID);
        #pragma unroll 4
        for (int k4 = 0; k4 < 16; k4++) {
            float4 wv = whh[k4];
            #pragma unroll
            for (int a = 0; a < AB; a++) {
                float4 zv = *(const float4*)&z_sm[a][192 + k4 * 4];
                acc[a] = fmaf(wv.x, zv.x, fmaf(wv.y, zv.y,
                         fmaf(wv.z, zv.z, fmaf(wv.w, zv.w, acc[a]))));
            }
        }
        float bb = b_ih[g] + b_hh[g];
        #pragma unroll
        for (int a = 0; a < AB; a++) g_sm[a][g] = acc[a] + bb;
    }
    __syncthreads();
    // ---- LSTM pointwise update ----
    for (int w = tid; w < AB * HID; w += TPB) {
        int a = w >> 6, d = w & 63;
        int i = ab + a;
        float gi = g_sm[a][d],       gf = g_sm[a][64 + d];
        float gg = g_sm[a][128 + d], go = g_sm[a][192 + d];
        float c = d_c[i * HID + d];
        c = sigm(gf) * c + sigm(gi) * tanhf(gg);
        float h = sigm(go) * tanhf(c);
        d_c[i * HID + d]  = c;
        hnxt[i * HID + d] = h;
        cv_sm[a][d] = h;                        // stage for output projection
    }
    __syncthreads();
    // ---- out = (W_out @ h_new + b_out) * mask ----
    if (tid < AB * 2) {
        int a = tid >> 1, oo = tid & 1;
        int i = ab + a;
        float acc = b_out[oo];
        #pragma unroll 8
        for (int k = 0; k < HID; k++) acc = fmaf(W_out[oo * HID + k], cv_sm[a][k], acc);
        out[(t * N_AG + i) * 2 + oo] = acc * mrow[i];
    }
}

// ---------------- launch -----------------------------------------------------
extern "C" void kernel_launch(void* const* d_in, const int* in_sizes, int n_in,
                              void* d_out, int out_size)
{
    // Robust input identification (tolerates presence/absence of scalar inputs):
    // W_soc has unique element count 36864; weights follow setup_inputs order around it.
    int iWsoc = -1, iX = -1, iM = -1, iH = -1, iC = -1;
    for (int i = 0; i < n_in; i++) {
        int s = in_sizes[i];
        if (s == 36864 && iWsoc < 0) iWsoc = i;   // W_soc [64,576]
        if (s == 98304 && iX < 0)    iX = i;      // X (first; Y comes later)
        if (s == 49152 && iM < 0)    iM = i;      // part_masks (before W_ih which is also 49152)
        if (s == 131072) { if (iH < 0) iH = i; else if (iC < 0) iC = i; }
    }
    const float* X     = (const float*)d_in[iX];
    const float* masks = (const float*)d_in[iM];
    const float* h0    = (const float*)d_in[iH];
    const float* c0    = (const float*)d_in[iC];
    const float* W_in  = (const float*)d_in[iWsoc - 2];
    const float* b_in  = (const float*)d_in[iWsoc - 1];
    const float* W_soc = (const float*)d_in[iWsoc];
    const float* b_soc = (const float*)d_in[iWsoc + 1];
    const float* W_ih  = (const float*)d_in[iWsoc + 2];
    const float* W_hh  = (const float*)d_in[iWsoc + 3];
    const float* b_ih  = (const float*)d_in[iWsoc + 4];
    const float* b_hh  = (const float*)d_in[iWsoc + 5];
    const float* W_out = (const float*)d_in[iWsoc + 6];
    const float* b_out = (const float*)d_in[iWsoc + 7];
    float* out = (float*)d_out;

    init_kernel<<<512, 256>>>(h0, c0, W_soc, out);
    nbr_kernel<<<NSTEP * 8, 256>>>(X, masks);
    for (int t = 0; t < NSTEP; t++)
        step_kernel<<<N_AG / AB, TPB>>>(t, X, masks, W_in, b_in, b_soc,
                                        W_ih, W_hh, b_ih, b_hh, W_out, b_out, out);
}

// round 4
// speedup vs baseline: 1.1619x; 1.1619x over previous
#include <cuda_runtime.h>
#include <math.h>

#define N_AG   2048
#define HID    64
#define MED    128
#define SOC    64
#define ZK     256     // z layout: r[0:128] | e[128:192] | h[192:256]
#define NGATE  256
#define NSTEP  20
#define MAXNB  32
#define AB     16      // agents per block
#define TPB    512     // step kernel threads (2 halves x 256 gates)

// ---------------- device scratch (static, no runtime alloc) ----------------
__device__ float d_h[2 * N_AG * HID];          // double-buffered hidden state
__device__ float d_c[N_AG * HID];              // cell state
__device__ float d_Wse[SOC * HID];             // collapsed social weight (sum over 9 window cells)
__device__ float4 d_Wt4[64 * NGATE];           // K-major interleaved gate weights: [k4][g] = W(4k4..4k4+3, g)
__device__ float d_bg[NGATE];                  // b_ih + b_hh
__device__ int   d_nbc[NSTEP * N_AG];          // neighbor counts per (t, agent)
__device__ int   d_nbi[NSTEP * N_AG * MAXNB];  // neighbor indices (ascending j)

__device__ __forceinline__ float sigm(float x) { return 1.0f / (1.0f + expf(-x)); }

// ---------------- init: copy h0/c0, collapse W_soc, build Wt4/bg, zero tail
__global__ __launch_bounds__(256) void init_kernel(
    const float* __restrict__ h0, const float* __restrict__ c0,
    const float* __restrict__ W_soc,
    const float* __restrict__ W_ih, const float* __restrict__ W_hh,
    const float* __restrict__ b_ih, const float* __restrict__ b_hh,
    float* __restrict__ out)
{
    int i = blockIdx.x * blockDim.x + threadIdx.x;
    if (i < N_AG * HID) { d_h[i] = h0[i]; d_c[i] = c0[i]; }
    if (i < SOC * HID) {
        int o = i >> 6, k = i & 63;
        float s = 0.f;
        #pragma unroll
        for (int w = 0; w < 9; w++) s += W_soc[o * 576 + w * 64 + k];
        d_Wse[i] = s;
    }
    if (i < 64 * NGATE) {
        int k4 = i >> 8, g = i & 255;
        float v[4];
        #pragma unroll
        for (int j = 0; j < 4; j++) {
            int k = k4 * 4 + j;
            v[j] = (k < 192) ? W_ih[g * 192 + k] : W_hh[g * 64 + (k - 192)];
        }
        d_Wt4[i] = make_float4(v[0], v[1], v[2], v[3]);
    }
    if (i < NGATE) d_bg[i] = b_ih[i] + b_hh[i];
    if (i < 4 * N_AG * 2) out[NSTEP * N_AG * 2 + i] = 0.f;  // frames 20..23 = 0
}

// ---------------- neighbor precompute: grid = NSTEP*8 blocks ---------------
// Replicates ref exactly: lt = min(coords) - 1.2f; p = floor((c-lt)/0.3f);
// masked -> cell (0,0); agent i gathers cell p_i - (1,1).
__global__ __launch_bounds__(256) void nbr_kernel(
    const float* __restrict__ X, const float* __restrict__ masks)
{
    int t    = blockIdx.x >> 3;
    int pass = blockIdx.x & 7;
    __shared__ __align__(16) int keys[N_AG];
    __shared__ float rmin[16];
    const float* xt = X + t * N_AG * 2;
    int tid = threadIdx.x;

    float mnx = 3.4e38f, mny = 3.4e38f;
    for (int i = tid; i < N_AG; i += 256) {
        mnx = fminf(mnx, xt[2 * i]);
        mny = fminf(mny, xt[2 * i + 1]);
    }
    #pragma unroll
    for (int o = 16; o; o >>= 1) {
        mnx = fminf(mnx, __shfl_xor_sync(0xffffffffu, mnx, o));
        mny = fminf(mny, __shfl_xor_sync(0xffffffffu, mny, o));
    }
    if ((tid & 31) == 0) { rmin[tid >> 5] = mnx; rmin[8 + (tid >> 5)] = mny; }
    __syncthreads();
    if (tid == 0) {
        float a = rmin[0], b = rmin[8];
        for (int w = 1; w < 8; w++) { a = fminf(a, rmin[w]); b = fminf(b, rmin[8 + w]); }
        rmin[0] = a - 1.2f;  // margin = 2*N_SIZE*CELL = 1.2 (fp32)
        rmin[8] = b - 1.2f;
    }
    __syncthreads();
    float ltx = rmin[0], lty = rmin[8];

    for (int i = tid; i < N_AG; i += 256) {
        int p0 = (int)floorf(__fdiv_rn(xt[2 * i]     - ltx, 0.3f));
        int p1 = (int)floorf(__fdiv_rn(xt[2 * i + 1] - lty, 0.3f));
        if (masks[t * N_AG + i] == 0.0f) { p0 = 0; p1 = 0; }
        keys[i] = p0 * 32768 + p1;
    }
    __syncthreads();

    int i = pass * 256 + tid;
    int q = keys[i] - 32769;         // key of cell (p0-1, p1-1); masked -> negative, no match
    int cnt = 0;
    int* dst = d_nbi + (t * N_AG + i) * MAXNB;
    const int4* k4 = (const int4*)keys;
    for (int j4 = 0; j4 < N_AG / 4; j4++) {
        int4 kv = k4[j4];
        int j = j4 * 4;
        if (kv.x == q && cnt < MAXNB) dst[cnt++] = j;
        if (kv.y == q && cnt < MAXNB) dst[cnt++] = j + 1;
        if (kv.z == q && cnt < MAXNB) dst[cnt++] = j + 2;
        if (kv.w == q && cnt < MAXNB) dst[cnt++] = j + 3;
    }
    d_nbc[t * N_AG + i] = cnt;
}

// ---------------- fused per-step kernel ------------------------------------
// grid = 128 blocks x 512 threads; block owns 16 agents.
// Gate GEMM: thread (g = tid&255, half = tid>>8) computes gate g over
// K-range [half*128, half*128+128) for all 16 agents; halves sum in smem.
__global__ __launch_bounds__(TPB) void step_kernel(
    int t,
    const float* __restrict__ X, const float* __restrict__ masks,
    const float* __restrict__ W_in, const float* __restrict__ b_in,
    const float* __restrict__ b_soc,
    const float* __restrict__ W_out, const float* __restrict__ b_out,
    float* out)
{
    __shared__ __align__(16) float z_sm[AB][ZK];     // [r | e | h] per agent (16KB)
    __shared__ float g_sm[AB][NGATE];                // gate accumulators (16KB)
    __shared__ float cv_sm[AB][HID];                 // cell_val, later h_new (4KB)

    int tid = threadIdx.x;
    int ab  = blockIdx.x * AB;
    const float* hcur = d_h + (t & 1) * N_AG * HID;
    float*       hnxt = d_h + ((t + 1) & 1) * N_AG * HID;
    const float* mrow = masks + t * N_AG;
    // ref: frames 0..10 feed X[t]; frames >=11 feed out[t-2] (faithful off-by-one)
    const float* xin = (t <= 10) ? (X + t * N_AG * 2) : (out + (t - 2) * N_AG * 2);

    // ---- social gather (cell_val) + stage h into z tail ----
    for (int w = tid; w < AB * HID; w += TPB) {
        int a = w >> 6, d = w & 63;
        int i = ab + a;
        int cnt = d_nbc[t * N_AG + i];
        const int* nb = d_nbi + (t * N_AG + i) * MAXNB;
        float s = 0.f;
        for (int jj = 0; jj < cnt; jj++) s += hcur[nb[jj] * HID + d];
        cv_sm[a][d] = s * mrow[i];
        z_sm[a][192 + d] = hcur[i * HID + d];
    }
    // ---- r = relu(W_in @ x + b_in) ----
    for (int w = tid; w < AB * MED; w += TPB) {
        int a = w >> 7, o = w & 127;
        int i = ab + a;
        float v = fmaf(W_in[o * 2], xin[i * 2],
                  fmaf(W_in[o * 2 + 1], xin[i * 2 + 1], b_in[o]));
        z_sm[a][o] = fmaxf(v, 0.f);
    }
    __syncthreads();
    // ---- e = relu(W_eff @ cell_val + b_soc) ----
    for (int w = tid; w < AB * SOC; w += TPB) {
        int a = w >> 6, o = w & 63;
        float acc = b_soc[o];
        const float* Ws = d_Wse + o * HID;
        #pragma unroll 8
        for (int k = 0; k < HID; k++) acc = fmaf(Ws[k], cv_sm[a][k], acc);
        z_sm[a][MED + o] = fmaxf(acc, 0.f);
    }
    __syncthreads();
    // ---- gate GEMM (K-split across halves, coalesced K-major weights) ----
    {
        int g = tid & 255, half = tid >> 8;
        float acc[AB];
        #pragma unroll
        for (int a = 0; a < AB; a++) acc[a] = 0.f;
        const float4* Wp = d_Wt4 + half * 32 * NGATE + g;   // [k4][g], lanes contiguous
        int kbase = half * 128;
        #pragma unroll 4
        for (int m = 0; m < 32; m++) {
            float4 wv = Wp[m * NGATE];
            int k = kbase + m * 4;
            #pragma unroll
            for (int a = 0; a < AB; a++) {
                float4 zv = *(const float4*)&z_sm[a][k];    // warp-broadcast LDS.128
                acc[a] = fmaf(wv.x, zv.x, fmaf(wv.y, zv.y,
                         fmaf(wv.z, zv.z, fmaf(wv.w, zv.w, acc[a]))));
            }
        }
        if (half == 0) {
            float bb = d_bg[g];
            #pragma unroll
            for (int a = 0; a < AB; a++) g_sm[a][g] = acc[a] + bb;
        }
        __syncthreads();
        if (half == 1) {
            #pragma unroll
            for (int a = 0; a < AB; a++) g_sm[a][g] += acc[a];
        }
    }
    __syncthreads();
    // ---- LSTM pointwise update ----
    for (int w = tid; w < AB * HID; w += TPB) {
        int a = w >> 6, d = w & 63;
        int i = ab + a;
        float gi = g_sm[a][d],       gf = g_sm[a][64 + d];
        float gg = g_sm[a][128 + d], go = g_sm[a][192 + d];
        float c = d_c[i * HID + d];
        c = sigm(gf) * c + sigm(gi) * tanhf(gg);
        float h = sigm(go) * tanhf(c);
        d_c[i * HID + d]  = c;
        hnxt[i * HID + d] = h;
        cv_sm[a][d] = h;
    }
    __syncthreads();
    // ---- out = (W_out @ h_new + b_out) * mask ----
    if (tid < AB * 2) {
        int a = tid >> 1, oo = tid & 1;
        int i = ab + a;
        float acc = b_out[oo];
        #pragma unroll 8
        for (int k = 0; k < HID; k++) acc = fmaf(W_out[oo * HID + k], cv_sm[a][k], acc);
        out[(t * N_AG + i) * 2 + oo] = acc * mrow[i];
    }
}

// ---------------- launch -----------------------------------------------------
extern "C" void kernel_launch(void* const* d_in, const int* in_sizes, int n_in,
                              void* d_out, int out_size)
{
    // W_soc has unique element count 36864; weights follow setup_inputs order around it.
    int iWsoc = -1, iX = -1, iM = -1, iH = -1, iC = -1;
    for (int i = 0; i < n_in; i++) {
        int s = in_sizes[i];
        if (s == 36864 && iWsoc < 0) iWsoc = i;   // W_soc [64,576]
        if (s == 98304 && iX < 0)    iX = i;      // X (first; Y comes later)
        if (s == 49152 && iM < 0)    iM = i;      // part_masks (before W_ih also 49152)
        if (s == 131072) { if (iH < 0) iH = i; else if (iC < 0) iC = i; }
    }
    const float* X     = (const float*)d_in[iX];
    const float* masks = (const float*)d_in[iM];
    const float* h0    = (const float*)d_in[iH];
    const float* c0    = (const float*)d_in[iC];
    const float* W_in  = (const float*)d_in[iWsoc - 2];
    const float* b_in  = (const float*)d_in[iWsoc - 1];
    const float* W_soc = (const float*)d_in[iWsoc];
    const float* b_soc = (const float*)d_in[iWsoc + 1];
    const float* W_ih  = (const float*)d_in[iWsoc + 2];
    const float* W_hh  = (const float*)d_in[iWsoc + 3];
    const float* b_ih  = (const float*)d_in[iWsoc + 4];
    const float* b_hh  = (const float*)d_in[iWsoc + 5];
    const float* W_out = (const float*)d_in[iWsoc + 6];
    const float* b_out = (const float*)d_in[iWsoc + 7];
    float* out = (float*)d_out;

    init_kernel<<<512, 256>>>(h0, c0, W_soc, W_ih, W_hh, b_ih, b_hh, out);
    nbr_kernel<<<NSTEP * 8, 256>>>(X, masks);
    for (int t = 0; t < NSTEP; t++)
        step_kernel<<<N_AG / AB, TPB>>>(t, X, masks, W_in, b_in, b_soc,
                                        W_out, b_out, out);
}

// round 5
// speedup vs baseline: 1.1666x; 1.0040x over previous
#include <cuda_runtime.h>
#include <math.h>

#define N_AG   2048
#define HID    64
#define MED    128
#define SOC    64
#define ZK     256     // z layout: r[0:128] | e[128:192] | h[192:256]
#define NGATE  256
#define NSTEP  20
#define MAXNB  32
#define AB     16      // agents per block
#define TPB    512

// ---------------- device scratch (static, no runtime alloc) ----------------
__device__ float d_h[2 * N_AG * HID];          // double-buffered hidden state
__device__ float d_c[N_AG * HID];              // cell state
__device__ float d_Wse[SOC * HID];             // collapsed social weight (sum over 9 window cells)
__device__ float4 d_Wt4[64 * NGATE];           // K-major interleaved gate weights: [k4][g]
__device__ float d_bg[NGATE];                  // b_ih + b_hh
__device__ int   d_nbc[NSTEP * N_AG];          // neighbor counts per (t, agent)
__device__ int   d_nbi[NSTEP * N_AG * MAXNB];  // neighbor indices (ascending j)

__device__ __forceinline__ float sigm(float x) { return 1.0f / (1.0f + expf(-x)); }

// ---------------- init: copy h0/c0, collapse W_soc, build Wt4/bg, zero tail
__global__ __launch_bounds__(256) void init_kernel(
    const float* __restrict__ h0, const float* __restrict__ c0,
    const float* __restrict__ W_soc,
    const float* __restrict__ W_ih, const float* __restrict__ W_hh,
    const float* __restrict__ b_ih, const float* __restrict__ b_hh,
    float* __restrict__ out)
{
    int i = blockIdx.x * blockDim.x + threadIdx.x;
    if (i < N_AG * HID) { d_h[i] = h0[i]; d_c[i] = c0[i]; }
    if (i < SOC * HID) {
        int o = i >> 6, k = i & 63;
        float s = 0.f;
        #pragma unroll
        for (int w = 0; w < 9; w++) s += W_soc[o * 576 + w * 64 + k];
        d_Wse[i] = s;
    }
    if (i < 64 * NGATE) {
        int k4 = i >> 8, g = i & 255;
        float v[4];
        #pragma unroll
        for (int j = 0; j < 4; j++) {
            int k = k4 * 4 + j;
            v[j] = (k < 192) ? W_ih[g * 192 + k] : W_hh[g * 64 + (k - 192)];
        }
        d_Wt4[i] = make_float4(v[0], v[1], v[2], v[3]);
    }
    if (i < NGATE) d_bg[i] = b_ih[i] + b_hh[i];
    if (i < 4 * N_AG * 2) out[NSTEP * N_AG * 2 + i] = 0.f;  // frames 20..23 = 0
}

// ---------------- neighbor precompute: grid = NSTEP*8 blocks ---------------
// Replicates ref exactly: lt = min(coords) - 1.2f; p = floor((c-lt)/0.3f);
// masked -> cell (0,0); agent i gathers cell p_i - (1,1).
__global__ __launch_bounds__(256) void nbr_kernel(
    const float* __restrict__ X, const float* __restrict__ masks)
{
    int t    = blockIdx.x >> 3;
    int pass = blockIdx.x & 7;
    __shared__ __align__(16) int keys[N_AG];
    __shared__ float rmin[16];
    const float* xt = X + t * N_AG * 2;
    int tid = threadIdx.x;

    float mnx = 3.4e38f, mny = 3.4e38f;
    for (int i = tid; i < N_AG; i += 256) {
        mnx = fminf(mnx, xt[2 * i]);
        mny = fminf(mny, xt[2 * i + 1]);
    }
    #pragma unroll
    for (int o = 16; o; o >>= 1) {
        mnx = fminf(mnx, __shfl_xor_sync(0xffffffffu, mnx, o));
        mny = fminf(mny, __shfl_xor_sync(0xffffffffu, mny, o));
    }
    if ((tid & 31) == 0) { rmin[tid >> 5] = mnx; rmin[8 + (tid >> 5)] = mny; }
    __syncthreads();
    if (tid == 0) {
        float a = rmin[0], b = rmin[8];
        for (int w = 1; w < 8; w++) { a = fminf(a, rmin[w]); b = fminf(b, rmin[8 + w]); }
        rmin[0] = a - 1.2f;  // margin = 2*N_SIZE*CELL = 1.2 (fp32)
        rmin[8] = b - 1.2f;
    }
    __syncthreads();
    float ltx = rmin[0], lty = rmin[8];

    for (int i = tid; i < N_AG; i += 256) {
        int p0 = (int)floorf(__fdiv_rn(xt[2 * i]     - ltx, 0.3f));
        int p1 = (int)floorf(__fdiv_rn(xt[2 * i + 1] - lty, 0.3f));
        if (masks[t * N_AG + i] == 0.0f) { p0 = 0; p1 = 0; }
        keys[i] = p0 * 32768 + p1;
    }
    __syncthreads();

    int i = pass * 256 + tid;
    int q = keys[i] - 32769;         // key of cell (p0-1, p1-1); masked -> negative, no match
    int cnt = 0;
    int* dst = d_nbi + (t * N_AG + i) * MAXNB;
    const int4* k4 = (const int4*)keys;
    for (int j4 = 0; j4 < N_AG / 4; j4++) {
        int4 kv = k4[j4];
        int j = j4 * 4;
        if (kv.x == q && cnt < MAXNB) dst[cnt++] = j;
        if (kv.y == q && cnt < MAXNB) dst[cnt++] = j + 1;
        if (kv.z == q && cnt < MAXNB) dst[cnt++] = j + 2;
        if (kv.w == q && cnt < MAXNB) dst[cnt++] = j + 3;
    }
    d_nbc[t * N_AG + i] = cnt;
}

// ---------------- fused per-step kernel ------------------------------------
// grid = 128 blocks x 512 threads; block owns 16 agents.
// Gate GEMM tiling: thread (gq = tid&63, half = (tid>>6)&1, ag = tid>>7)
// computes gates {gq, gq+64, gq+128, gq+192} x agents {4ag..4ag+3} over
// K-range [half*128, half*128+128); halves combine in smem.
__global__ __launch_bounds__(TPB) void step_kernel(
    int t,
    const float* __restrict__ X, const float* __restrict__ masks,
    const float* __restrict__ W_in, const float* __restrict__ b_in,
    const float* __restrict__ b_soc,
    const float* __restrict__ W_out, const float* __restrict__ b_out,
    float* out)
{
    __shared__ __align__(16) float z_sm[AB][ZK];     // [r | e | h] per agent (16KB)
    __shared__ float g_sm[AB][NGATE];                // gate accumulators (16KB)
    __shared__ float cv_sm[AB][HID];                 // cell_val, later h_new (4KB)

    int tid = threadIdx.x;
    int ab  = blockIdx.x * AB;
    const float* hcur = d_h + (t & 1) * N_AG * HID;
    float*       hnxt = d_h + ((t + 1) & 1) * N_AG * HID;
    const float* mrow = masks + t * N_AG;
    // ref: frames 0..10 feed X[t]; frames >=11 feed out[t-2] (faithful off-by-one)
    const float* xin = (t <= 10) ? (X + t * N_AG * 2) : (out + (t - 2) * N_AG * 2);

    // ---- social gather (cell_val) + stage h into z tail ----
    for (int w = tid; w < AB * HID; w += TPB) {
        int a = w >> 6, d = w & 63;
        int i = ab + a;
        int cnt = d_nbc[t * N_AG + i];
        const int* nb = d_nbi + (t * N_AG + i) * MAXNB;
        float s = 0.f;
        for (int jj = 0; jj < cnt; jj++) s += hcur[nb[jj] * HID + d];
        cv_sm[a][d] = s * mrow[i];
        z_sm[a][192 + d] = hcur[i * HID + d];
    }
    // ---- r = relu(W_in @ x + b_in) ----
    for (int w = tid; w < AB * MED; w += TPB) {
        int a = w >> 7, o = w & 127;
        int i = ab + a;
        float v = fmaf(W_in[o * 2], xin[i * 2],
                  fmaf(W_in[o * 2 + 1], xin[i * 2 + 1], b_in[o]));
        z_sm[a][o] = fmaxf(v, 0.f);
    }
    __syncthreads();
    // ---- e = relu(W_eff @ cell_val + b_soc) ----
    for (int w = tid; w < AB * SOC; w += TPB) {
        int a = w >> 6, o = w & 63;
        float acc = b_soc[o];
        const float* Ws = d_Wse + o * HID;
        #pragma unroll 8
        for (int k = 0; k < HID; k++) acc = fmaf(Ws[k], cv_sm[a][k], acc);
        z_sm[a][MED + o] = fmaxf(acc, 0.f);
    }
    __syncthreads();
    // ---- gate GEMM: 4 gates x 4 agents per thread, K split in 2 halves ----
    {
        int gq   = tid & 63;
        int half = (tid >> 6) & 1;
        int ag   = tid >> 7;                 // agent group 0..3
        int a0   = ag * 4;

        float acc[4][4];
        #pragma unroll
        for (int q = 0; q < 4; q++)
            #pragma unroll
            for (int a = 0; a < 4; a++) acc[q][a] = 0.f;

        const float4* Wp = d_Wt4 + half * 32 * NGATE + gq;   // [k4][g], lanes contiguous
        int kb = half * 128;

        #pragma unroll 2
        for (int m = 0; m < 32; m++) {
            float4 wv0 = Wp[m * NGATE];
            float4 wv1 = Wp[m * NGATE + 64];
            float4 wv2 = Wp[m * NGATE + 128];
            float4 wv3 = Wp[m * NGATE + 192];
            int k = kb + m * 4;
            #pragma unroll
            for (int a = 0; a < 4; a++) {
                float4 zv = *(const float4*)&z_sm[a0 + a][k];   // warp-broadcast LDS.128
                acc[0][a] = fmaf(wv0.x, zv.x, fmaf(wv0.y, zv.y,
                            fmaf(wv0.z, zv.z, fmaf(wv0.w, zv.w, acc[0][a]))));
                acc[1][a] = fmaf(wv1.x, zv.x, fmaf(wv1.y, zv.y,
                            fmaf(wv1.z, zv.z, fmaf(wv1.w, zv.w, acc[1][a]))));
                acc[2][a] = fmaf(wv2.x, zv.x, fmaf(wv2.y, zv.y,
                            fmaf(wv2.z, zv.z, fmaf(wv2.w, zv.w, acc[2][a]))));
                acc[3][a] = fmaf(wv3.x, zv.x, fmaf(wv3.y, zv.y,
                            fmaf(wv3.z, zv.z, fmaf(wv3.w, zv.w, acc[3][a]))));
            }
        }
        if (half == 0) {
            #pragma unroll
            for (int q = 0; q < 4; q++) {
                float bb = d_bg[gq + q * 64];
                #pragma unroll
                for (int a = 0; a < 4; a++)
                    g_sm[a0 + a][gq + q * 64] = acc[q][a] + bb;
            }
        }
        __syncthreads();
        if (half == 1) {
            #pragma unroll
            for (int q = 0; q < 4; q++)
                #pragma unroll
                for (int a = 0; a < 4; a++)
                    g_sm[a0 + a][gq + q * 64] += acc[q][a];
        }
    }
    __syncthreads();
    // ---- LSTM pointwise update ----
    for (int w = tid; w < AB * HID; w += TPB) {
        int a = w >> 6, d = w & 63;
        int i = ab + a;
        float gi = g_sm[a][d],       gf = g_sm[a][64 + d];
        float gg = g_sm[a][128 + d], go = g_sm[a][192 + d];
        float c = d_c[i * HID + d];
        c = sigm(gf) * c + sigm(gi) * tanhf(gg);
        float h = sigm(go) * tanhf(c);
        d_c[i * HID + d]  = c;
        hnxt[i * HID + d] = h;
        cv_sm[a][d] = h;
    }
    __syncthreads();
    // ---- out = (W_out @ h_new + b_out) * mask ----
    if (tid < AB * 2) {
        int a = tid >> 1, oo = tid & 1;
        int i = ab + a;
        float acc = b_out[oo];
        #pragma unroll 8
        for (int k = 0; k < HID; k++) acc = fmaf(W_out[oo * HID + k], cv_sm[a][k], acc);
        out[(t * N_AG + i) * 2 + oo] = acc * mrow[i];
    }
}

// ---------------- launch -----------------------------------------------------
extern "C" void kernel_launch(void* const* d_in, const int* in_sizes, int n_in,
                              void* d_out, int out_size)
{
    // W_soc has unique element count 36864; weights follow setup_inputs order around it.
    int iWsoc = -1, iX = -1, iM = -1, iH = -1, iC = -1;
    for (int i = 0; i < n_in; i++) {
        int s = in_sizes[i];
        if (s == 36864 && iWsoc < 0) iWsoc = i;   // W_soc [64,576]
        if (s == 98304 && iX < 0)    iX = i;      // X (first; Y comes later)
        if (s == 49152 && iM < 0)    iM = i;      // part_masks (before W_ih also 49152)
        if (s == 131072) { if (iH < 0) iH = i; else if (iC < 0) iC = i; }
    }
    const float* X     = (const float*)d_in[iX];
    const float* masks = (const float*)d_in[iM];
    const float* h0    = (const float*)d_in[iH];
    const float* c0    = (const float*)d_in[iC];
    const float* W_in  = (const float*)d_in[iWsoc - 2];
    const float* b_in  = (const float*)d_in[iWsoc - 1];
    const float* W_soc = (const float*)d_in[iWsoc];
    const float* b_soc = (const float*)d_in[iWsoc + 1];
    const float* W_ih  = (const float*)d_in[iWsoc + 2];
    const float* W_hh  = (const float*)d_in[iWsoc + 3];
    const float* b_ih  = (const float*)d_in[iWsoc + 4];
    const float* b_hh  = (const float*)d_in[iWsoc + 5];
    const float* W_out = (const float*)d_in[iWsoc + 6];
    const float* b_out = (const float*)d_in[iWsoc + 7];
    float* out = (float*)d_out;

    init_kernel<<<512, 256>>>(h0, c0, W_soc, W_ih, W_hh, b_ih, b_hh, out);
    nbr_kernel<<<NSTEP * 8, 256>>>(X, masks);
    for (int t = 0; t < NSTEP; t++)
        step_kernel<<<N_AG / AB, TPB>>>(t, X, masks, W_in, b_in, b_soc,
                                        W_out, b_out, out);
}

// round 6
// speedup vs baseline: 1.2355x; 1.0591x over previous
#include <cuda_runtime.h>
#include <math.h>

#define N_AG   2048
#define HID    64
#define MED    128
#define SOC    64
#define ZK     256     // z layout: r[0:128] | e[128:192] | h[192:256]
#define NGATE  256
#define NSTEP  20
#define MAXNB  32
#define AB     16      // agents per block
#define TPB    1024    // 64 gq x 4 kq x 4 agent-groups

// ---------------- device scratch (static, no runtime alloc) ----------------
__device__ float d_h[2 * N_AG * HID];          // double-buffered hidden state
__device__ float d_c[N_AG * HID];              // cell state
__device__ float d_Wse[SOC * HID];             // collapsed social weight (sum over 9 window cells)
__device__ float4 d_Wt4[64 * NGATE];           // K-major interleaved gate weights: [k4][g]
__device__ float d_bg[NGATE];                  // b_ih + b_hh
__device__ int   d_nbc[NSTEP * N_AG];          // neighbor counts per (t, agent)
__device__ int   d_nbi[NSTEP * N_AG * MAXNB];  // neighbor indices (ascending j)

__device__ __forceinline__ float sigm(float x) { return 1.0f / (1.0f + expf(-x)); }

// ---------------- init: copy h0/c0, collapse W_soc, build Wt4/bg, zero tail
__global__ __launch_bounds__(256) void init_kernel(
    const float* __restrict__ h0, const float* __restrict__ c0,
    const float* __restrict__ W_soc,
    const float* __restrict__ W_ih, const float* __restrict__ W_hh,
    const float* __restrict__ b_ih, const float* __restrict__ b_hh,
    float* __restrict__ out)
{
    int i = blockIdx.x * blockDim.x + threadIdx.x;
    if (i < N_AG * HID) { d_h[i] = h0[i]; d_c[i] = c0[i]; }
    if (i < SOC * HID) {
        int o = i >> 6, k = i & 63;
        float s = 0.f;
        #pragma unroll
        for (int w = 0; w < 9; w++) s += W_soc[o * 576 + w * 64 + k];
        d_Wse[i] = s;
    }
    if (i < 64 * NGATE) {
        int k4 = i >> 8, g = i & 255;
        float v[4];
        #pragma unroll
        for (int j = 0; j < 4; j++) {
            int k = k4 * 4 + j;
            v[j] = (k < 192) ? W_ih[g * 192 + k] : W_hh[g * 64 + (k - 192)];
        }
        d_Wt4[i] = make_float4(v[0], v[1], v[2], v[3]);
    }
    if (i < NGATE) d_bg[i] = b_ih[i] + b_hh[i];
    if (i < 4 * N_AG * 2) out[NSTEP * N_AG * 2 + i] = 0.f;  // frames 20..23 = 0
}

// ---------------- neighbor precompute: grid = NSTEP*8 blocks ---------------
// Replicates ref exactly: lt = min(coords) - 1.2f; p = floor((c-lt)/0.3f);
// masked -> cell (0,0); agent i gathers cell p_i - (1,1).
__global__ __launch_bounds__(256) void nbr_kernel(
    const float* __restrict__ X, const float* __restrict__ masks)
{
    int t    = blockIdx.x >> 3;
    int pass = blockIdx.x & 7;
    __shared__ __align__(16) int keys[N_AG];
    __shared__ float rmin[16];
    const float* xt = X + t * N_AG * 2;
    int tid = threadIdx.x;

    float mnx = 3.4e38f, mny = 3.4e38f;
    for (int i = tid; i < N_AG; i += 256) {
        mnx = fminf(mnx, xt[2 * i]);
        mny = fminf(mny, xt[2 * i + 1]);
    }
    #pragma unroll
    for (int o = 16; o; o >>= 1) {
        mnx = fminf(mnx, __shfl_xor_sync(0xffffffffu, mnx, o));
        mny = fminf(mny, __shfl_xor_sync(0xffffffffu, mny, o));
    }
    if ((tid & 31) == 0) { rmin[tid >> 5] = mnx; rmin[8 + (tid >> 5)] = mny; }
    __syncthreads();
    if (tid == 0) {
        float a = rmin[0], b = rmin[8];
        for (int w = 1; w < 8; w++) { a = fminf(a, rmin[w]); b = fminf(b, rmin[8 + w]); }
        rmin[0] = a - 1.2f;  // margin = 2*N_SIZE*CELL = 1.2 (fp32)
        rmin[8] = b - 1.2f;
    }
    __syncthreads();
    float ltx = rmin[0], lty = rmin[8];

    for (int i = tid; i < N_AG; i += 256) {
        int p0 = (int)floorf(__fdiv_rn(xt[2 * i]     - ltx, 0.3f));
        int p1 = (int)floorf(__fdiv_rn(xt[2 * i + 1] - lty, 0.3f));
        if (masks[t * N_AG + i] == 0.0f) { p0 = 0; p1 = 0; }
        keys[i] = p0 * 32768 + p1;
    }
    __syncthreads();

    int i = pass * 256 + tid;
    int q = keys[i] - 32769;         // key of cell (p0-1, p1-1); masked -> negative, no match
    int cnt = 0;
    int* dst = d_nbi + (t * N_AG + i) * MAXNB;
    const int4* k4 = (const int4*)keys;
    for (int j4 = 0; j4 < N_AG / 4; j4++) {
        int4 kv = k4[j4];
        int j = j4 * 4;
        if (kv.x == q && cnt < MAXNB) dst[cnt++] = j;
        if (kv.y == q && cnt < MAXNB) dst[cnt++] = j + 1;
        if (kv.z == q && cnt < MAXNB) dst[cnt++] = j + 2;
        if (kv.w == q && cnt < MAXNB) dst[cnt++] = j + 3;
    }
    d_nbc[t * N_AG + i] = cnt;
}

// ---------------- fused per-step kernel ------------------------------------
// grid = 128 blocks x 1024 threads; block owns 16 agents.
// Gate GEMM tiling: thread (gq = tid&63, kq = (tid>>6)&3, ag = tid>>8)
// computes gates {gq, gq+64, gq+128, gq+192} x agents {4ag..4ag+3} over
// K-range [kq*64, kq*64+64). Partials combine pairwise:
//   kq0 -> g_sm (+bias), kq2 -> g2_sm; sync; kq1 += g_sm, kq3 += g2_sm;
//   LSTM reads g_sm + g2_sm.
__global__ __launch_bounds__(TPB, 1) void step_kernel(
    int t,
    const float* __restrict__ X, const float* __restrict__ masks,
    const float* __restrict__ W_in, const float* __restrict__ b_in,
    const float* __restrict__ b_soc,
    const float* __restrict__ W_out, const float* __restrict__ b_out,
    float* out)
{
    __shared__ __align__(16) float z_sm[AB][ZK];     // [r | e | h] per agent (16KB)
    __shared__ float g_sm[AB][NGATE];                // gate partials K[0:128] (16KB)
    __shared__ float g2_sm[AB][NGATE];               // gate partials K[128:256] (16KB)
    __shared__ float cv_sm[AB][HID];                 // cell_val, later h_new (4KB)

    int tid = threadIdx.x;
    int ab  = blockIdx.x * AB;
    const float* hcur = d_h + (t & 1) * N_AG * HID;
    float*       hnxt = d_h + ((t + 1) & 1) * N_AG * HID;
    const float* mrow = masks + t * N_AG;
    // ref: frames 0..10 feed X[t]; frames >=11 feed out[t-2] (faithful off-by-one)
    const float* xin = (t <= 10) ? (X + t * N_AG * 2) : (out + (t - 2) * N_AG * 2);

    // ---- social gather (cell_val) + stage h into z tail: 1024 items ----
    {
        int w = tid;  // AB*HID == TPB
        int a = w >> 6, d = w & 63;
        int i = ab + a;
        int cnt = d_nbc[t * N_AG + i];
        const int* nb = d_nbi + (t * N_AG + i) * MAXNB;
        float s = 0.f;
        for (int jj = 0; jj < cnt; jj++) s += hcur[nb[jj] * HID + d];
        cv_sm[a][d] = s * mrow[i];
        z_sm[a][192 + d] = hcur[i * HID + d];
    }
    // ---- r = relu(W_in @ x + b_in): 2048 items ----
    for (int w = tid; w < AB * MED; w += TPB) {
        int a = w >> 7, o = w & 127;
        int i = ab + a;
        float v = fmaf(W_in[o * 2], xin[i * 2],
                  fmaf(W_in[o * 2 + 1], xin[i * 2 + 1], b_in[o]));
        z_sm[a][o] = fmaxf(v, 0.f);
    }
    __syncthreads();
    // ---- e = relu(W_eff @ cell_val + b_soc): 1024 items ----
    {
        int w = tid;
        int a = w >> 6, o = w & 63;
        float acc = b_soc[o];
        const float* Ws = d_Wse + o * HID;
        #pragma unroll 8
        for (int k = 0; k < HID; k++) acc = fmaf(Ws[k], cv_sm[a][k], acc);
        z_sm[a][MED + o] = fmaxf(acc, 0.f);
    }
    __syncthreads();
    // ---- gate GEMM: 4 gates x 4 agents x 64 K per thread ----
    {
        int gq = tid & 63;
        int kq = (tid >> 6) & 3;             // K-quarter 0..3
        int ag = tid >> 8;                   // agent group 0..3
        int a0 = ag * 4;

        float acc[4][4];
        #pragma unroll
        for (int q = 0; q < 4; q++)
            #pragma unroll
            for (int a = 0; a < 4; a++) acc[q][a] = 0.f;

        const float4* Wp = d_Wt4 + kq * 16 * NGATE + gq;   // [k4][g], lanes contiguous
        int kb = kq * 64;

        #pragma unroll 2
        for (int m = 0; m < 16; m++) {
            float4 wv0 = Wp[m * NGATE];
            float4 wv1 = Wp[m * NGATE + 64];
            float4 wv2 = Wp[m * NGATE + 128];
            float4 wv3 = Wp[m * NGATE + 192];
            int k = kb + m * 4;
            #pragma unroll
            for (int a = 0; a < 4; a++) {
                float4 zv = *(const float4*)&z_sm[a0 + a][k];   // warp-broadcast LDS.128
                acc[0][a] = fmaf(wv0.x, zv.x, fmaf(wv0.y, zv.y,
                            fmaf(wv0.z, zv.z, fmaf(wv0.w, zv.w, acc[0][a]))));
                acc[1][a] = fmaf(wv1.x, zv.x, fmaf(wv1.y, zv.y,
                            fmaf(wv1.z, zv.z, fmaf(wv1.w, zv.w, acc[1][a]))));
                acc[2][a] = fmaf(wv2.x, zv.x, fmaf(wv2.y, zv.y,
                            fmaf(wv2.z, zv.z, fmaf(wv2.w, zv.w, acc[2][a]))));
                acc[3][a] = fmaf(wv3.x, zv.x, fmaf(wv3.y, zv.y,
                            fmaf(wv3.z, zv.z, fmaf(wv3.w, zv.w, acc[3][a]))));
            }
        }
        if (kq == 0) {
            #pragma unroll
            for (int q = 0; q < 4; q++) {
                float bb = d_bg[gq + q * 64];
                #pragma unroll
                for (int a = 0; a < 4; a++)
                    g_sm[a0 + a][gq + q * 64] = acc[q][a] + bb;
            }
        } else if (kq == 2) {
            #pragma unroll
            for (int q = 0; q < 4; q++)
                #pragma unroll
                for (int a = 0; a < 4; a++)
                    g2_sm[a0 + a][gq + q * 64] = acc[q][a];
        }
        __syncthreads();
        if (kq == 1) {
            #pragma unroll
            for (int q = 0; q < 4; q++)
                #pragma unroll
                for (int a = 0; a < 4; a++)
                    g_sm[a0 + a][gq + q * 64] += acc[q][a];
        } else if (kq == 3) {
            #pragma unroll
            for (int q = 0; q < 4; q++)
                #pragma unroll
                for (int a = 0; a < 4; a++)
                    g2_sm[a0 + a][gq + q * 64] += acc[q][a];
        }
    }
    __syncthreads();
    // ---- LSTM pointwise update: 1024 items ----
    {
        int w = tid;
        int a = w >> 6, d = w & 63;
        int i = ab + a;
        float gi = g_sm[a][d]       + g2_sm[a][d];
        float gf = g_sm[a][64 + d]  + g2_sm[a][64 + d];
        float gg = g_sm[a][128 + d] + g2_sm[a][128 + d];
        float go = g_sm[a][192 + d] + g2_sm[a][192 + d];
        float c = d_c[i * HID + d];
        c = sigm(gf) * c + sigm(gi) * tanhf(gg);
        float h = sigm(go) * tanhf(c);
        d_c[i * HID + d]  = c;
        hnxt[i * HID + d] = h;
        cv_sm[a][d] = h;
    }
    __syncthreads();
    // ---- out = (W_out @ h_new + b_out) * mask ----
    if (tid < AB * 2) {
        int a = tid >> 1, oo = tid & 1;
        int i = ab + a;
        float acc = b_out[oo];
        #pragma unroll 8
        for (int k = 0; k < HID; k++) acc = fmaf(W_out[oo * HID + k], cv_sm[a][k], acc);
        out[(t * N_AG + i) * 2 + oo] = acc * mrow[i];
    }
}

// ---------------- launch -----------------------------------------------------
extern "C" void kernel_launch(void* const* d_in, const int* in_sizes, int n_in,
                              void* d_out, int out_size)
{
    // W_soc has unique element count 36864; weights follow setup_inputs order around it.
    int iWsoc = -1, iX = -1, iM = -1, iH = -1, iC = -1;
    for (int i = 0; i < n_in; i++) {
        int s = in_sizes[i];
        if (s == 36864 && iWsoc < 0) iWsoc = i;   // W_soc [64,576]
        if (s == 98304 && iX < 0)    iX = i;      // X (first; Y comes later)
        if (s == 49152 && iM < 0)    iM = i;      // part_masks (before W_ih also 49152)
        if (s == 131072) { if (iH < 0) iH = i; else if (iC < 0) iC = i; }
    }
    const float* X     = (const float*)d_in[iX];
    const float* masks = (const float*)d_in[iM];
    const float* h0    = (const float*)d_in[iH];
    const float* c0    = (const float*)d_in[iC];
    const float* W_in  = (const float*)d_in[iWsoc - 2];
    const float* b_in  = (const float*)d_in[iWsoc - 1];
    const float* W_soc = (const float*)d_in[iWsoc];
    const float* b_soc = (const float*)d_in[iWsoc + 1];
    const float* W_ih  = (const float*)d_in[iWsoc + 2];
    const float* W_hh  = (const float*)d_in[iWsoc + 3];
    const float* b_ih  = (const float*)d_in[iWsoc + 4];
    const float* b_hh  = (const float*)d_in[iWsoc + 5];
    const float* W_out = (const float*)d_in[iWsoc + 6];
    const float* b_out = (const float*)d_in[iWsoc + 7];
    float* out = (float*)d_out;

    init_kernel<<<512, 256>>>(h0, c0, W_soc, W_ih, W_hh, b_ih, b_hh, out);
    nbr_kernel<<<NSTEP * 8, 256>>>(X, masks);
    for (int t = 0; t < NSTEP; t++)
        step_kernel<<<N_AG / AB, TPB>>>(t, X, masks, W_in, b_in, b_soc,
                                        W_out, b_out, out);
}

// round 7
// speedup vs baseline: 3.2233x; 2.6089x over previous
#include <cuda_runtime.h>
#include <math.h>

#define N_AG   2048
#define HID    64
#define MED    128
#define SOC    64
#define ZK     256     // z layout: r[0:128] | e[128:192] | h[192:256]
#define NGATE  256
#define NSTEP  20
#define MAXNB  32
#define AB     16      // agents per block
#define TPB    1024
#define NBLK   (N_AG / AB)   // 128 blocks, all co-resident (1/SM)

// ---------------- device scratch (static, no runtime alloc) ----------------
__device__ float d_h[2 * N_AG * HID];          // double-buffered hidden state
__device__ float d_c[N_AG * HID];              // cell state
__device__ float d_Wse[HID * SOC];             // collapsed social weight, K-major: [k][o]
__device__ float4 d_Wt4[64 * NGATE];           // K-major interleaved gate weights: [k4][g]
__device__ float d_bg[NGATE];                  // b_ih + b_hh
__device__ int   d_nbc[NSTEP * N_AG];          // neighbor counts per (t, agent)
__device__ int   d_nbi[NSTEP * N_AG * MAXNB];  // neighbor indices (ascending j)
__device__ unsigned g_bar;                     // grid-barrier arrive counter (monotonic)
__device__ unsigned g_rel;                     // grid-barrier release generation

__device__ __forceinline__ float sigm(float x) { return 1.0f / (1.0f + expf(-x)); }

// ---------------- init: copy h0/c0, collapse+transpose W_soc, build Wt4/bg,
// zero tail frames, reset grid barrier (must run every replay) ---------------
__global__ __launch_bounds__(256) void init_kernel(
    const float* __restrict__ h0, const float* __restrict__ c0,
    const float* __restrict__ W_soc,
    const float* __restrict__ W_ih, const float* __restrict__ W_hh,
    const float* __restrict__ b_ih, const float* __restrict__ b_hh,
    float* __restrict__ out)
{
    int i = blockIdx.x * blockDim.x + threadIdx.x;
    if (i == 0) { g_bar = 0u; g_rel = 0u; }
    if (i < N_AG * HID) { d_h[i] = h0[i]; d_c[i] = c0[i]; }
    if (i < SOC * HID) {
        int o = i & 63, k = i >> 6;
        float s = 0.f;
        #pragma unroll
        for (int w = 0; w < 9; w++) s += W_soc[o * 576 + w * 64 + k];
        d_Wse[k * 64 + o] = s;                 // K-major: lanes (o) contiguous
    }
    if (i < 64 * NGATE) {
        int k4 = i >> 8, g = i & 255;
        float v[4];
        #pragma unroll
        for (int j = 0; j < 4; j++) {
            int k = k4 * 4 + j;
            v[j] = (k < 192) ? W_ih[g * 192 + k] : W_hh[g * 64 + (k - 192)];
        }
        d_Wt4[i] = make_float4(v[0], v[1], v[2], v[3]);
    }
    if (i < NGATE) d_bg[i] = b_ih[i] + b_hh[i];
    if (i < 4 * N_AG * 2) out[NSTEP * N_AG * 2 + i] = 0.f;  // frames 20..23 = 0
}

// ---------------- neighbor precompute: grid = NSTEP*8 blocks ---------------
// Replicates ref exactly: lt = min(coords) - 1.2f; p = floor((c-lt)/0.3f);
// masked -> cell (0,0); agent i gathers cell p_i - (1,1).
__global__ __launch_bounds__(256) void nbr_kernel(
    const float* __restrict__ X, const float* __restrict__ masks)
{
    int t    = blockIdx.x >> 3;
    int pass = blockIdx.x & 7;
    __shared__ __align__(16) int keys[N_AG];
    __shared__ float rmin[16];
    const float* xt = X + t * N_AG * 2;
    int tid = threadIdx.x;

    float mnx = 3.4e38f, mny = 3.4e38f;
    for (int i = tid; i < N_AG; i += 256) {
        mnx = fminf(mnx, xt[2 * i]);
        mny = fminf(mny, xt[2 * i + 1]);
    }
    #pragma unroll
    for (int o = 16; o; o >>= 1) {
        mnx = fminf(mnx, __shfl_xor_sync(0xffffffffu, mnx, o));
        mny = fminf(mny, __shfl_xor_sync(0xffffffffu, mny, o));
    }
    if ((tid & 31) == 0) { rmin[tid >> 5] = mnx; rmin[8 + (tid >> 5)] = mny; }
    __syncthreads();
    if (tid == 0) {
        float a = rmin[0], b = rmin[8];
        for (int w = 1; w < 8; w++) { a = fminf(a, rmin[w]); b = fminf(b, rmin[8 + w]); }
        rmin[0] = a - 1.2f;  // margin = 2*N_SIZE*CELL = 1.2 (fp32)
        rmin[8] = b - 1.2f;
    }
    __syncthreads();
    float ltx = rmin[0], lty = rmin[8];

    for (int i = tid; i < N_AG; i += 256) {
        int p0 = (int)floorf(__fdiv_rn(xt[2 * i]     - ltx, 0.3f));
        int p1 = (int)floorf(__fdiv_rn(xt[2 * i + 1] - lty, 0.3f));
        if (masks[t * N_AG + i] == 0.0f) { p0 = 0; p1 = 0; }
        keys[i] = p0 * 32768 + p1;
    }
    __syncthreads();

    int i = pass * 256 + tid;
    int q = keys[i] - 32769;         // key of cell (p0-1, p1-1); masked -> negative, no match
    int cnt = 0;
    int* dst = d_nbi + (t * N_AG + i) * MAXNB;
    const int4* k4 = (const int4*)keys;
    for (int j4 = 0; j4 < N_AG / 4; j4++) {
        int4 kv = k4[j4];
        int j = j4 * 4;
        if (kv.x == q && cnt < MAXNB) dst[cnt++] = j;
        if (kv.y == q && cnt < MAXNB) dst[cnt++] = j + 1;
        if (kv.z == q && cnt < MAXNB) dst[cnt++] = j + 2;
        if (kv.w == q && cnt < MAXNB) dst[cnt++] = j + 3;
    }
    d_nbc[t * N_AG + i] = cnt;
}

// ---------------- persistent kernel: all 20 steps in one launch ------------
// grid = 128 blocks x 1024 threads; block owns 16 agents; 1 block/SM so all
// blocks are co-resident -> software grid barrier between steps is safe.
// Only h crosses blocks (out[t-2] feedback is block-local).
__global__ __launch_bounds__(TPB, 1) void persist_kernel(
    const float* __restrict__ X, const float* __restrict__ masks,
    const float* __restrict__ W_in, const float* __restrict__ b_in,
    const float* __restrict__ b_soc,
    const float* __restrict__ W_out, const float* __restrict__ b_out,
    float* out)
{
    __shared__ __align__(16) float z_sm[AB][ZK];     // [r | e | h] per agent (16KB)
    __shared__ float g_sm[AB][NGATE];                // gate partials K[0:128] (16KB)
    __shared__ float g2_sm[AB][NGATE];               // gate partials K[128:256] (16KB)
    __shared__ float cv_sm[AB][HID];                 // cell_val, later h_new (4KB)

    int tid = threadIdx.x;
    int ab  = blockIdx.x * AB;

    for (int t = 0; t < NSTEP; t++) {
        const float* hcur = d_h + (t & 1) * N_AG * HID;
        float*       hnxt = d_h + ((t + 1) & 1) * N_AG * HID;
        const float* mrow = masks + t * N_AG;
        // ref: frames 0..10 feed X[t]; frames >=11 feed out[t-2]
        const float* xin = (t <= 10) ? (X + t * N_AG * 2) : (out + (t - 2) * N_AG * 2);

        // ---- social gather (cell_val) + stage h into z tail: 1024 items ----
        {
            int a = tid >> 6, d = tid & 63;
            int i = ab + a;
            int cnt = d_nbc[t * N_AG + i];
            const int* nb = d_nbi + (t * N_AG + i) * MAXNB;
            float s = 0.f;
            for (int jj = 0; jj < cnt; jj++) s += hcur[nb[jj] * HID + d];
            cv_sm[a][d] = s * mrow[i];
            z_sm[a][192 + d] = hcur[i * HID + d];
        }
        // ---- r = relu(W_in @ x + b_in): 2048 items ----
        for (int w = tid; w < AB * MED; w += TPB) {
            int a = w >> 7, o = w & 127;
            int i = ab + a;
            float v = fmaf(W_in[o * 2], xin[i * 2],
                      fmaf(W_in[o * 2 + 1], xin[i * 2 + 1], b_in[o]));
            z_sm[a][o] = fmaxf(v, 0.f);
        }
        __syncthreads();
        // ---- e = relu(W_eff @ cell_val + b_soc), K-major weights ----
        {
            int a = tid >> 6, o = tid & 63;
            float acc = b_soc[o];
            #pragma unroll 16
            for (int k = 0; k < HID; k++)
                acc = fmaf(d_Wse[k * 64 + o], cv_sm[a][k], acc);  // coalesced LDG
            z_sm[a][MED + o] = fmaxf(acc, 0.f);
        }
        __syncthreads();
        // ---- gate GEMM: 4 gates x 4 agents x 64 K per thread ----
        {
            int gq = tid & 63;
            int kq = (tid >> 6) & 3;             // K-quarter 0..3
            int ag = tid >> 8;                   // agent group 0..3
            int a0 = ag * 4;

            float acc[4][4];
            #pragma unroll
            for (int q = 0; q < 4; q++)
                #pragma unroll
                for (int a = 0; a < 4; a++) acc[q][a] = 0.f;

            const float4* Wp = d_Wt4 + kq * 16 * NGATE + gq;   // lanes contiguous
            int kb = kq * 64;

            #pragma unroll 2
            for (int m = 0; m < 16; m++) {
                float4 wv0 = Wp[m * NGATE];
                float4 wv1 = Wp[m * NGATE + 64];
                float4 wv2 = Wp[m * NGATE + 128];
                float4 wv3 = Wp[m * NGATE + 192];
                int k = kb + m * 4;
                #pragma unroll
                for (int a = 0; a < 4; a++) {
                    float4 zv = *(const float4*)&z_sm[a0 + a][k];  // warp broadcast
                    acc[0][a] = fmaf(wv0.x, zv.x, fmaf(wv0.y, zv.y,
                                fmaf(wv0.z, zv.z, fmaf(wv0.w, zv.w, acc[0][a]))));
                    acc[1][a] = fmaf(wv1.x, zv.x, fmaf(wv1.y, zv.y,
                                fmaf(wv1.z, zv.z, fmaf(wv1.w, zv.w, acc[1][a]))));
                    acc[2][a] = fmaf(wv2.x, zv.x, fmaf(wv2.y, zv.y,
                                fmaf(wv2.z, zv.z, fmaf(wv2.w, zv.w, acc[2][a]))));
                    acc[3][a] = fmaf(wv3.x, zv.x, fmaf(wv3.y, zv.y,
                                fmaf(wv3.z, zv.z, fmaf(wv3.w, zv.w, acc[3][a]))));
                }
            }
            if (kq == 0) {
                #pragma unroll
                for (int q = 0; q < 4; q++) {
                    float bb = d_bg[gq + q * 64];
                    #pragma unroll
                    for (int a = 0; a < 4; a++)
                        g_sm[a0 + a][gq + q * 64] = acc[q][a] + bb;
                }
            } else if (kq == 2) {
                #pragma unroll
                for (int q = 0; q < 4; q++)
                    #pragma unroll
                    for (int a = 0; a < 4; a++)
                        g2_sm[a0 + a][gq + q * 64] = acc[q][a];
            }
            __syncthreads();
            if (kq == 1) {
                #pragma unroll
                for (int q = 0; q < 4; q++)
                    #pragma unroll
                    for (int a = 0; a < 4; a++)
                        g_sm[a0 + a][gq + q * 64] += acc[q][a];
            } else if (kq == 3) {
                #pragma unroll
                for (int q = 0; q < 4; q++)
                    #pragma unroll
                    for (int a = 0; a < 4; a++)
                        g2_sm[a0 + a][gq + q * 64] += acc[q][a];
            }
        }
        __syncthreads();
        // ---- LSTM pointwise update: 1024 items ----
        {
            int a = tid >> 6, d = tid & 63;
            int i = ab + a;
            float gi = g_sm[a][d]       + g2_sm[a][d];
            float gf = g_sm[a][64 + d]  + g2_sm[a][64 + d];
            float gg = g_sm[a][128 + d] + g2_sm[a][128 + d];
            float go = g_sm[a][192 + d] + g2_sm[a][192 + d];
            float c = d_c[i * HID + d];
            c = sigm(gf) * c + sigm(gi) * tanhf(gg);
            float h = sigm(go) * tanhf(c);
            d_c[i * HID + d]  = c;
            hnxt[i * HID + d] = h;
            cv_sm[a][d] = h;
        }
        __syncthreads();
        // ---- out = (W_out @ h_new + b_out) * mask ----
        if (tid < AB * 2) {
            int a = tid >> 1, oo = tid & 1;
            int i = ab + a;
            float acc = b_out[oo];
            #pragma unroll 8
            for (int k = 0; k < HID; k++) acc = fmaf(W_out[oo * HID + k], cv_sm[a][k], acc);
            out[(t * N_AG + i) * 2 + oo] = acc * mrow[i];
        }
        // ---- grid barrier: publish hnxt before any block's next gather ----
        __syncthreads();
        if (tid == 0) {
            __threadfence();
            unsigned prev = atomicAdd(&g_bar, 1u);
            unsigned target = (unsigned)(t + 1);
            if (prev == (unsigned)NBLK * target - 1u) {
                atomicExch(&g_rel, target);          // release
            } else {
                while (*((volatile unsigned*)&g_rel) < target) { }
            }
            __threadfence();
        }
        __syncthreads();
    }
}

// ---------------- launch -----------------------------------------------------
extern "C" void kernel_launch(void* const* d_in, const int* in_sizes, int n_in,
                              void* d_out, int out_size)
{
    // W_soc has unique element count 36864; weights follow setup_inputs order around it.
    int iWsoc = -1, iX = -1, iM = -1, iH = -1, iC = -1;
    for (int i = 0; i < n_in; i++) {
        int s = in_sizes[i];
        if (s == 36864 && iWsoc < 0) iWsoc = i;   // W_soc [64,576]
        if (s == 98304 && iX < 0)    iX = i;      // X (first; Y comes later)
        if (s == 49152 && iM < 0)    iM = i;      // part_masks (before W_ih also 49152)
        if (s == 131072) { if (iH < 0) iH = i; else if (iC < 0) iC = i; }
    }
    const float* X     = (const float*)d_in[iX];
    const float* masks = (const float*)d_in[iM];
    const float* h0    = (const float*)d_in[iH];
    const float* c0    = (const float*)d_in[iC];
    const float* W_in  = (const float*)d_in[iWsoc - 2];
    const float* b_in  = (const float*)d_in[iWsoc - 1];
    const float* W_soc = (const float*)d_in[iWsoc];
    const float* b_soc = (const float*)d_in[iWsoc + 1];
    const float* W_ih  = (const float*)d_in[iWsoc + 2];
    const float* W_hh  = (const float*)d_in[iWsoc + 3];
    const float* b_ih  = (const float*)d_in[iWsoc + 4];
    const float* b_hh  = (const float*)d_in[iWsoc + 5];
    const float* W_out = (const float*)d_in[iWsoc + 6];
    const float* b_out = (const float*)d_in[iWsoc + 7];
    float* out = (float*)d_out;

    init_kernel<<<512, 256>>>(h0, c0, W_soc, W_ih, W_hh, b_ih, b_hh, out);
    nbr_kernel<<<NSTEP * 8, 256>>>(X, masks);
    persist_kernel<<<NBLK, TPB>>>(X, masks, W_in, b_in, b_soc, W_out, b_out, out);
}